// round 4
// baseline (speedup 1.0000x reference)
#include <cuda_runtime.h>
#include <cuda_bf16.h>
#include <cstdint>
#include <math.h>

#define BB 128
#define TT 512
#define II 256
#define HH 1024
#define GG 4096
#define CC 1000
#define KTOT 1280
#define NCHUNK 20          // K chunks of 64
#define NCTA 128

// Dynamic SMEM layout (offsets from 128B-aligned base):
//   Whi [32][1280] bf16 swizzled : 81920
//   Wlo                          : 81920
//   A double buf: 2 x (Ahi 16K + Alo 16K) = 65536
#define W_HI 0u
#define W_LO 81920u
#define A_BUF 163840u
#define ABUF_STRIDE 32768u
#define SMEM_DYN (229376 + 256)

// ---------------- device globals (no dynamic alloc) ---------------------------
__device__ __align__(16) __nv_bfloat16 g_Wh[GG * KTOT];
__device__ __align__(16) __nv_bfloat16 g_Wl[GG * KTOT];
__device__ __align__(16) __nv_bfloat16 g_xh[TT * BB * II];   // [t][m][k]
__device__ __align__(16) __nv_bfloat16 g_xl[TT * BB * II];
__device__ __align__(16) __nv_bfloat16 g_hh[2][BB * HH];
__device__ __align__(16) __nv_bfloat16 g_hl[2][BB * HH];
__device__ float g_c[BB * HH];
__device__ float g_bs[GG];
__device__ unsigned g_bar_cnt;
__device__ unsigned g_bar_flag;

// ---------------- helpers ------------------------------------------------------
__device__ __forceinline__ uint32_t smem_u32(const void* p) {
    uint32_t a;
    asm("{ .reg .u64 t; cvta.to.shared.u64 t, %1; cvt.u32.u64 %0, t; }" : "=r"(a) : "l"(p));
    return a;
}
__device__ __forceinline__ void cp16(uint32_t saddr, const void* gaddr) {
    asm volatile("cp.async.cg.shared.global [%0], [%1], 16;" :: "r"(saddr), "l"(gaddr) : "memory");
}
__device__ __forceinline__ void ldsm4(uint32_t addr, uint32_t& r0, uint32_t& r1,
                                      uint32_t& r2, uint32_t& r3) {
    asm volatile("ldmatrix.sync.aligned.m8n8.x4.shared.b16 {%0,%1,%2,%3}, [%4];"
                 : "=r"(r0), "=r"(r1), "=r"(r2), "=r"(r3) : "r"(addr));
}
__device__ __forceinline__ void mma16816(float* c, const uint32_t* a, uint32_t b0, uint32_t b1) {
    asm volatile(
        "mma.sync.aligned.m16n8k16.row.col.f32.bf16.bf16.f32 "
        "{%0,%1,%2,%3}, {%4,%5,%6,%7}, {%8,%9}, {%0,%1,%2,%3};"
        : "+f"(c[0]), "+f"(c[1]), "+f"(c[2]), "+f"(c[3])
        : "r"(a[0]), "r"(a[1]), "r"(a[2]), "r"(a[3]), "r"(b0), "r"(b1));
}

// ---------------- prep kernels -------------------------------------------------
// Stored row r = nb*32 + hc*4 + q  <->  original row q*H + nb*8 + hc (nb = CTA id).
__global__ void prep_w(const float* __restrict__ Wih, const float* __restrict__ Whh) {
    int idx = blockIdx.x * blockDim.x + threadIdx.x;
    if (idx >= GG * KTOT) return;
    int r = idx / KTOT, k = idx - r * KTOT;
    int nb = r >> 5, j = r & 31, hc = j >> 2, q = j & 3;
    int orig = q * HH + nb * 8 + hc;
    float v = (k < II) ? Wih[(size_t)orig * II + k] : Whh[(size_t)orig * HH + (k - II)];
    __nv_bfloat16 hi = __float2bfloat16(v);
    g_Wh[idx] = hi;
    g_Wl[idx] = __float2bfloat16(v - __bfloat162float(hi));
}

__global__ void prep_x(const float* __restrict__ x) {
    int idx = blockIdx.x * blockDim.x + threadIdx.x;
    if (idx >= TT * BB * II) return;
    int t = idx / (BB * II);
    int rem = idx - t * (BB * II);
    int m = rem / II, k = rem - m * II;
    float v = x[((size_t)m * TT + t) * II + k];
    __nv_bfloat16 hi = __float2bfloat16(v);
    g_xh[idx] = hi;
    g_xl[idx] = __float2bfloat16(v - __bfloat162float(hi));
}

__global__ void prep_misc(const float* __restrict__ bih, const float* __restrict__ bhh) {
    int i = blockIdx.x * blockDim.x + threadIdx.x;
    if (i < BB * HH) {
        g_hh[0][i] = __float2bfloat16(0.f);
        g_hl[0][i] = __float2bfloat16(0.f);
        g_c[i] = 0.f;
    }
    if (i < GG) g_bs[i] = bih[i] + bhh[i];
    if (i == 0) { g_bar_cnt = 0u; g_bar_flag = 0u; }
}

// ---------------- grid barrier (all CTAs resident: grid=128 <= 148 SMs) --------
__device__ __forceinline__ void bar_arrive(unsigned step) {
    if (threadIdx.x == 0) {
        unsigned v;
        asm volatile("atom.release.gpu.global.add.u32 %0, [%1], 1;"
                     : "=r"(v) : "l"(&g_bar_cnt) : "memory");
        if (v == NCTA * (step + 1) - 1) {
            asm volatile("st.release.gpu.global.u32 [%0], %1;"
                         :: "l"(&g_bar_flag), "r"(step + 1) : "memory");
        }
    }
}
__device__ __forceinline__ void bar_wait(unsigned step) {   // wait flag >= step
    if (threadIdx.x == 0) {
        unsigned f;
        while (true) {
            asm volatile("ld.acquire.gpu.global.u32 %0, [%1];"
                         : "=r"(f) : "l"(&g_bar_flag) : "memory");
            if (f >= step) break;
            __nanosleep(64);
        }
    }
    __syncthreads();
}

// ---------------- persistent LSTM kernel ---------------------------------------
// Grid 128 CTAs x 256 thr (8 warps = 4m x 2n). CTA: M=128 (all batch), N=32 gate
// cols = 8 h-cols (gate-interleaved). Warp tile 32x16 -> acc[2 mf][2 nf][4].
__global__ __launch_bounds__(256, 1) void lstm_persist() {
    extern __shared__ __align__(16) char dsm_raw[];
    const uint32_t dbase = (smem_u32(dsm_raw) + 127) & ~127u;

    const int tid = threadIdx.x;
    const int wid = tid >> 5, lid = tid & 31;
    const int wm = wid & 3, wn = wid >> 2;
    const int nb = blockIdx.x;
    const int mi = lid >> 3, lr = lid & 7;

    // ---- load this CTA's weight slice into SMEM (once) ----
    // 32 rows x 160 k-segs(16B) x {hi,lo}; swizzle (seg ^ (row&7)).
    for (int s = 0; s < 20; s++) {
        int idx = tid + 256 * s;           // 0..5119
        int row = idx / 160, seg = idx - row * 160;
        size_t go = (size_t)(nb * 32 + row) * KTOT + seg * 8;
        uint32_t so = (uint32_t)row * 2560u + (uint32_t)((seg ^ (row & 7)) << 4);
        cp16(dbase + W_HI + so, g_Wh + go);
        cp16(dbase + W_LO + so, g_Wl + go);
    }
    asm volatile("cp.async.commit_group;" ::: "memory");

    // ---- A chunk loader: 128 rows x 8 segs x {hi,lo} = 2048 x 16B ----
    auto load_chunk = [&](int kc, const __nv_bfloat16* hsh, const __nv_bfloat16* hsl,
                          const __nv_bfloat16* xsh, const __nv_bfloat16* xsl) {
        const uint32_t bofs = A_BUF + (uint32_t)(kc & 1) * ABUF_STRIDE;
        const int k0 = kc * 64;
        const bool xreg = (kc < 4);
#pragma unroll
        for (int s = 0; s < 8; s++) {
            int idx = tid + 256 * s;       // 0..2047
            int reg = idx >> 10;           // 0 hi, 1 lo
            int w = idx & 1023;
            int row = w >> 3, seg = w & 7;
            uint32_t sa = dbase + bofs + (uint32_t)reg * 16384u
                        + (uint32_t)row * 128u + (uint32_t)((seg ^ (row & 7)) << 4);
            const __nv_bfloat16* g;
            if (xreg) g = (reg ? xsl : xsh) + (size_t)row * II + k0 + seg * 8;
            else      g = (reg ? hsl : hsh) + (size_t)row * HH + (k0 - II) + seg * 8;
            cp16(sa, g);
        }
        asm volatile("cp.async.commit_group;" ::: "memory");
    };

    const int lq = lid & 3;
    const bool hasIF = (lq & 1) == 0;
    const int hcl = lq >> 1;

#pragma unroll 1
    for (int t = 0; t < TT; t++) {
        const __nv_bfloat16* __restrict__ hsh = g_hh[t & 1];
        const __nv_bfloat16* __restrict__ hsl = g_hl[t & 1];
        const __nv_bfloat16* __restrict__ xsh = g_xh + (size_t)t * (BB * II);
        const __nv_bfloat16* __restrict__ xsl = g_xl + (size_t)t * (BB * II);

        float acc[2][2][4];
#pragma unroll
        for (int a = 0; a < 2; a++)
#pragma unroll
            for (int b = 0; b < 2; b++)
#pragma unroll
                for (int i = 0; i < 4; i++) acc[a][b][i] = 0.f;

        load_chunk(0, hsh, hsl, xsh, xsl);
        load_chunk(1, hsh, hsl, xsh, xsl);

#pragma unroll 1
        for (int kc = 0; kc < NCHUNK; kc++) {
            if (kc + 1 < NCHUNK) asm volatile("cp.async.wait_group 1;" ::: "memory");
            else                 asm volatile("cp.async.wait_group 0;" ::: "memory");
            __syncthreads();

            const uint32_t abase = dbase + A_BUF + (uint32_t)(kc & 1) * ABUF_STRIDE;
#pragma unroll
            for (int ks = 0; ks < 4; ks++) {
                // B frags from resident W (row stride 2560B)
                uint32_t bh[4], bl[4];
                {
                    int brow = wn * 16 + (mi >> 1) * 8 + lr;
                    int ksegb = kc * 8 + ks * 2 + (mi & 1);
                    uint32_t bd = dbase + W_HI + (uint32_t)brow * 2560u
                                + (uint32_t)((ksegb ^ (brow & 7)) << 4);
                    ldsm4(bd, bh[0], bh[1], bh[2], bh[3]);
                    ldsm4(bd + W_LO, bl[0], bl[1], bl[2], bl[3]);
                }
                // A frags (two m16 tiles)
                uint32_t ah[2][4], al[2][4];
#pragma unroll
                for (int mf = 0; mf < 2; mf++) {
                    int arow = wm * 32 + mf * 16 + ((mi & 1) << 3) + lr;
                    int ksega = ks * 2 + (mi >> 1);
                    uint32_t ad = abase + (uint32_t)arow * 128u
                                + (uint32_t)((ksega ^ (arow & 7)) << 4);
                    ldsm4(ad, ah[mf][0], ah[mf][1], ah[mf][2], ah[mf][3]);
                    ldsm4(ad + 16384u, al[mf][0], al[mf][1], al[mf][2], al[mf][3]);
                }
#pragma unroll
                for (int mf = 0; mf < 2; mf++)
#pragma unroll
                    for (int nf = 0; nf < 2; nf++) {
                        mma16816(acc[mf][nf], ah[mf], bh[nf * 2], bh[nf * 2 + 1]);
                        mma16816(acc[mf][nf], ah[mf], bl[nf * 2], bl[nf * 2 + 1]);
                        mma16816(acc[mf][nf], al[mf], bh[nf * 2], bh[nf * 2 + 1]);
                    }
            }
            __syncthreads();
            if (kc + 2 < NCHUNK) {
                if (kc + 2 == 4) bar_wait((unsigned)t);   // h(t) ready before first h chunk
                load_chunk(kc + 2, hsh, hsl, xsh, xsl);
            }
        }

        // ---- epilogue: bias + LSTM update, write h(t+1) ----
        __nv_bfloat16* __restrict__ hh_o = g_hh[(t + 1) & 1];
        __nv_bfloat16* __restrict__ hl_o = g_hl[(t + 1) & 1];
#pragma unroll
        for (int mf = 0; mf < 2; mf++) {
            const int rbase = wm * 32 + mf * 16 + (lid >> 2);
#pragma unroll
            for (int nf = 0; nf < 2; nf++) {
                const int nglob = nb * 8 + wn * 4 + nf * 2 + hcl;
                const float bias0 = g_bs[(hasIF ? 0 : 2) * HH + nglob];
                const float bias1 = g_bs[(hasIF ? 1 : 3) * HH + nglob];
                float d0 = acc[mf][nf][0] + bias0;
                float d1 = acc[mf][nf][1] + bias1;
                float d2 = acc[mf][nf][2] + bias0;
                float d3 = acc[mf][nf][3] + bias1;
                float e0 = __shfl_xor_sync(0xFFFFFFFFu, d0, 1);
                float e1 = __shfl_xor_sync(0xFFFFFFFFu, d1, 1);
                float e2 = __shfl_xor_sync(0xFFFFFFFFu, d2, 1);
                float e3 = __shfl_xor_sync(0xFFFFFFFFu, d3, 1);
                if (hasIF) {
#pragma unroll
                    for (int r = 0; r < 2; r++) {
                        float gi = r ? d2 : d0, gf = r ? d3 : d1;
                        float gg = r ? e2 : e0, go = r ? e3 : e1;
                        float iv = 1.f / (1.f + expf(-gi));
                        float fv = 1.f / (1.f + expf(-gf));
                        float gv = tanhf(gg);
                        float ov = 1.f / (1.f + expf(-go));
                        size_t idx = (size_t)(rbase + r * 8) * HH + nglob;
                        float cn = fv * g_c[idx] + iv * gv;
                        g_c[idx] = cn;
                        float hv = ov * tanhf(cn);
                        __nv_bfloat16 hi = __float2bfloat16(hv);
                        hh_o[idx] = hi;
                        hl_o[idx] = __float2bfloat16(hv - __bfloat162float(hi));
                    }
                }
            }
        }
        __threadfence();
        __syncthreads();
        bar_arrive((unsigned)t);
    }
}

// ---------------- final FC ------------------------------------------------------
__global__ __launch_bounds__(256) void fc_kernel(
    const float* __restrict__ fcW, const float* __restrict__ fcb, float* __restrict__ out) {
    int w = blockIdx.x * 8 + (threadIdx.x >> 5);
    int lane = threadIdx.x & 31;
    if (w >= BB * CC) return;
    int b = w / CC, c = w - b * CC;
    const __nv_bfloat16* __restrict__ hh = g_hh[0] + (size_t)b * HH;   // TT even
    const __nv_bfloat16* __restrict__ hl = g_hl[0] + (size_t)b * HH;
    const float* __restrict__ wr = fcW + (size_t)c * HH;
    float s = 0.f;
#pragma unroll 4
    for (int k = lane; k < HH; k += 32)
        s += (__bfloat162float(hh[k]) + __bfloat162float(hl[k])) * wr[k];
#pragma unroll
    for (int o = 16; o; o >>= 1) s += __shfl_down_sync(0xFFFFFFFFu, s, o);
    if (lane == 0) out[b * CC + c] = s + fcb[c];
}

extern "C" void kernel_launch(void* const* d_in, const int* in_sizes, int n_in,
                              void* d_out, int out_size) {
    const float* x   = (const float*)d_in[0];
    const float* Wih = (const float*)d_in[1];
    const float* Whh = (const float*)d_in[2];
    const float* bih = (const float*)d_in[3];
    const float* bhh = (const float*)d_in[4];
    const float* fcW = (const float*)d_in[5];
    const float* fcb = (const float*)d_in[6];
    float* out = (float*)d_out;

    cudaFuncSetAttribute(lstm_persist, cudaFuncAttributeMaxDynamicSharedMemorySize, SMEM_DYN);

    prep_w<<<(GG * KTOT + 255) / 256, 256>>>(Wih, Whh);
    prep_x<<<(TT * BB * II + 255) / 256, 256>>>(x);
    prep_misc<<<(BB * HH + 255) / 256, 256>>>(bih, bhh);
    lstm_persist<<<NCTA, 256, SMEM_DYN>>>();
    fc_kernel<<<(BB * CC + 7) / 8, 256>>>(fcW, fcb, out);
}